// round 6
// baseline (speedup 1.0000x reference)
#include <cuda_runtime.h>
#include <math.h>

#define BATCH 512
#define FEAT  512
#define NS    255
#define NN    511
#define NCAND 21
#define SPLITK 8
#define CHUNK  64   // FEAT / SPLITK

__device__ float g_qsp[SPLITK][NS * BATCH];   // partial sums, [c][s][b]
__device__ float g_qnode[BATCH * NN];         // [b][n] (for clip)
__device__ float g_ga[NN * NCAND];
__device__ float g_sa0[NN];
__device__ float g_anode[NN];

// ========== K1: split-K GEMM, 64x64 tile, 4x4 micro-tile ==========
__global__ void __launch_bounds__(256) k_gemm(const float* __restrict__ x,
                                              const float* __restrict__ W) {
    __shared__ float xT[16][68];   // [k][b]
    __shared__ float ws[16][68];   // [k][s]
    int tid = threadIdx.x;
    int s0 = blockIdx.x * 64;
    int b0 = blockIdx.y * 64;
    int kbase = blockIdx.z * CHUNK;
    int tx = tid & 15;   // s quad
    int ty = tid >> 4;   // b quad
    float acc[4][4];
#pragma unroll
    for (int i = 0; i < 4; i++)
#pragma unroll
        for (int j = 0; j < 4; j++) acc[i][j] = 0.f;

    int lk = tid & 15;     // x-load: k
    int lb = tid >> 4;     // x-load: b base
    int lsw = tid & 63;    // w-load: s
    int lkw = tid >> 6;    // w-load: k base

    for (int k0 = 0; k0 < CHUNK; k0 += 16) {
#pragma unroll
        for (int i = 0; i < 4; i++) {
            xT[lk][lb + 16 * i] = x[(b0 + lb + 16 * i) * FEAT + kbase + k0 + lk];
            int s = s0 + lsw;
            int kk = lkw + 4 * i;
            ws[kk][lsw] = (s < NS) ? W[(kbase + k0 + kk) * NS + s] : 0.f;
        }
        __syncthreads();
#pragma unroll
        for (int kk = 0; kk < 16; kk++) {
            float4 xv = *(const float4*)&xT[kk][4 * ty];
            float4 wv = *(const float4*)&ws[kk][4 * tx];
            acc[0][0] += xv.x * wv.x; acc[0][1] += xv.x * wv.y;
            acc[0][2] += xv.x * wv.z; acc[0][3] += xv.x * wv.w;
            acc[1][0] += xv.y * wv.x; acc[1][1] += xv.y * wv.y;
            acc[1][2] += xv.y * wv.z; acc[1][3] += xv.y * wv.w;
            acc[2][0] += xv.z * wv.x; acc[2][1] += xv.z * wv.y;
            acc[2][2] += xv.z * wv.z; acc[2][3] += xv.z * wv.w;
            acc[3][0] += xv.w * wv.x; acc[3][1] += xv.w * wv.y;
            acc[3][2] += xv.w * wv.z; acc[3][3] += xv.w * wv.w;
        }
        __syncthreads();
    }
    float* dst = g_qsp[blockIdx.z];
#pragma unroll
    for (int j = 0; j < 4; j++) {
        int s = s0 + 4 * tx + j;
        if (s < NS) {
            float4 v = make_float4(acc[0][j], acc[1][j], acc[2][j], acc[3][j]);
            *(float4*)&dst[s * BATCH + b0 + 4 * ty] = v;
        }
    }
}

// ===== K2: fused chunk-sum + bias + ancestor-min + g_a + initial softmin =====
__global__ void __launch_bounds__(128) k_ga(const float* __restrict__ bias) {
    int n = blockIdx.x;        // 0..510
    int tid = threadIdx.x;     // 0..127
    float acc[NCAND];
#pragma unroll
    for (int j = 0; j < NCAND; j++) acc[j] = 0.f;

    // ancestor split chain of n (uniform across threads)
    int anc[8]; float sgn[8]; float bv[8]; int na = 0;
    {
        int a = n;
        while (a > 0) {
            int p = (a - 1) >> 1;
            anc[na] = p;
            sgn[na] = (a == 2 * p + 1) ? -1.f : 1.f;
            bv[na] = __ldg(&bias[p]);
            na++;
            a = p;
        }
    }
    const int CS = NS * BATCH;
#pragma unroll 4
    for (int e = 0; e < 4; e++) {
        int b = tid + 128 * e;
        float m = 1.0f;
        for (int k = 0; k < na; k++) {
            const float* col = &g_qsp[0][anc[k] * BATCH + b];
            float s_ = col[0];
#pragma unroll
            for (int c = 1; c < SPLITK; c++) s_ += col[c * CS];
            float q = s_ + bv[k];
            m = fminf(m, sgn[k] * q);
        }
        g_qnode[b * NN + n] = m;                       // scattered store (no stall)
        float th = m + 0.5f;
#pragma unroll
        for (int j = 0; j < NCAND; j++) {
            float aj = (float)j / 20.0f;
            float d = aj - th;
            acc[j] += (aj <= th) ? d * d : 0.f;
        }
    }
#pragma unroll
    for (int j = 0; j < NCAND; j++)
        for (int off = 16; off; off >>= 1)
            acc[j] += __shfl_down_sync(0xffffffffu, acc[j], off);
    __shared__ float part[4][NCAND];
    int lane = tid & 31, w = tid >> 5;
    if (lane == 0)
        for (int j = 0; j < NCAND; j++) part[w][j] = acc[j];
    __syncthreads();
    if (tid < 32) {
        const unsigned F = 0xffffffffu;
        float l = __int_as_float(0xff800000);
        if (tid < NCAND) {
            float s = part[0][tid] + part[1][tid] + part[2][tid] + part[3][tid];
            float aj = (float)tid / 20.0f;
            float v = 0.5f * aj * aj + 0.5f * s;
            g_ga[n * NCAND + tid] = v;
            l = -100.0f * v;
        }
        float m = l;
#pragma unroll
        for (int off = 16; off; off >>= 1) m = fmaxf(m, __shfl_xor_sync(F, m, off));
        float e = (tid < NCAND) ? expf(l - m) : 0.f;
        float S = e;
#pragma unroll
        for (int off = 16; off; off >>= 1) S += __shfl_xor_sync(F, S, off);
        float ww = e / S;
        float c = (tid < NCAND) ? ((float)tid / 20.0f) * ww : 0.f;
        float A = c;
#pragma unroll
        for (int off = 16; off; off >>= 1) A += __shfl_xor_sync(F, A, off);
        if (tid == 0) g_sa0[n] = A;
    }
}

// ============================ K3: single-warp sequential scan ============================
__global__ void __launch_bounds__(512) k_scan() {
    __shared__ float sa[NN];
    __shared__ float san[NN];
    __shared__ __align__(16) float viol[NN + 1];
    __shared__ float sct[NN];
    __shared__ float scp[NN];
    int tid = threadIdx.x;    // 512
    const unsigned F = 0xffffffffu;
    const float NEG_INF = __int_as_float(0xff800000);

    if (tid < NN) {
        sct[tid] = 1.f; scp[tid] = 0.f;
        float a = g_sa0[tid];
        sa[tid] = a;
        san[tid] = a;
    }
    if (tid == NN) viol[NN] = NEG_INF;
    float warm = 0.f;
    for (int i = tid; i < NN * NCAND; i += 512) warm += __ldg(&g_ga[i]);
    if (warm == -12345.6789f) g_anode[0] = warm;   // never true; keeps warm loads
    __syncthreads();
    if (tid < NN) viol[tid] = tid ? san[tid] - san[(tid - 1) >> 1] : san[0] - 1.f;
    __syncthreads();
    if (tid >= 32) return;

    int lane = tid;
    for (int it = 0; it < NN; ++it) {
        // ---- argmax over viol[0..510] (first-index tie), blocked 16/lane ----
        unsigned bkey = 0x007FFFFFu;
        int bidx = 1 << 30;
        float bval = NEG_INF;
        const float4* vp = (const float4*)&viol[lane * 16];
#pragma unroll
        for (int q = 0; q < 4; q++) {
            float4 f4 = vp[q];
#pragma unroll
            for (int c = 0; c < 4; c++) {
                float v = (c == 0) ? f4.x : (c == 1) ? f4.y : (c == 2) ? f4.z : f4.w;
                unsigned u = __float_as_uint(v);
                unsigned key = u ^ ((unsigned)((int)u >> 31) | 0x80000000u);
                if (key > bkey) { bkey = key; bidx = lane * 16 + q * 4 + c; bval = v; }
            }
        }
        unsigned mk = __reduce_max_sync(F, bkey);
        unsigned bal = __ballot_sync(F, bkey == mk);
        int src = __ffs(bal) - 1;
        int t = __shfl_sync(F, bidx, src);
        float bv = __shfl_sync(F, bval, src);
        if (!(bv <= 1e-8f) || t == 0) break;

        int p = (t - 1) >> 1;
        if (lane == 0) { sct[t] -= 1.f; scp[t] += 1.f; }
        __syncwarp();

        // ---- both softmins: lanes 0-6 -> group t, lanes 8-14 -> group p ----
        int g  = (lane < 8) ? t : p;
        int cl = lane & 7;
        bool act = (cl < 7) && (lane < 16);
        float l0 = NEG_INF, l1 = NEG_INF, l2 = NEG_INF;
        int j0 = cl * 3;
        if (act) {
            int L = 2 * g + 1, R = 2 * g + 2;
            float ct = sct[g];
            float cL = (L < NN) ? scp[L] : 0.f;
            float cR = (R < NN) ? scp[R] : 0.f;
            const float* gaG = &g_ga[g * NCAND];
            const float* gaL = (L < NN) ? &g_ga[L * NCAND] : gaG;
            const float* gaR = (R < NN) ? &g_ga[R * NCAND] : gaG;
            float g0 = ct * __ldg(&gaG[j0])     + cL * __ldg(&gaL[j0])     + cR * __ldg(&gaR[j0]);
            float g1 = ct * __ldg(&gaG[j0 + 1]) + cL * __ldg(&gaL[j0 + 1]) + cR * __ldg(&gaR[j0 + 1]);
            float g2 = ct * __ldg(&gaG[j0 + 2]) + cL * __ldg(&gaL[j0 + 2]) + cR * __ldg(&gaR[j0 + 2]);
            l0 = -100.0f * g0; l1 = -100.0f * g1; l2 = -100.0f * g2;
        }
        // group max via masked redux
        float m = 0.f;
        {
            float lm = fmaxf(l0, fmaxf(l1, l2));
            unsigned u = __float_as_uint(lm);
            unsigned key = u ^ ((unsigned)((int)u >> 31) | 0x80000000u);
            if (lane < 16) {
                unsigned msk = (lane < 8) ? 0x00FFu : 0xFF00u;
                unsigned mk2 = __reduce_max_sync(msk, key);
                unsigned uu = (mk2 & 0x80000000u) ? (mk2 ^ 0x80000000u) : ~mk2;
                m = __uint_as_float(uu);
            }
        }
        float e0 = act ? expf(l0 - m) : 0.f;
        float e1 = act ? expf(l1 - m) : 0.f;
        float e2 = act ? expf(l2 - m) : 0.f;
        float T1 = e0 + e1 + e2;
        float T2 = ((float)j0 / 20.0f) * e0
                 + ((float)(j0 + 1) / 20.0f) * e1
                 + ((float)(j0 + 2) / 20.0f) * e2;
        T1 += __shfl_xor_sync(F, T1, 1); T2 += __shfl_xor_sync(F, T2, 1);
        T1 += __shfl_xor_sync(F, T1, 2); T2 += __shfl_xor_sync(F, T2, 2);
        T1 += __shfl_xor_sync(F, T1, 4); T2 += __shfl_xor_sync(F, T2, 4);
        float C = T2 / T1;
        if (lane == 0) sa[t] = C;
        if (lane == 8) sa[p] = C;
        __syncwarp();

        // ---- combined a_node + viol updates (san recomputed on the fly from sa) ----
        int sib = 4 * p + 3 - t;
        if (lane < 11) {
            int i;
            switch (lane) {
                case 0:  i = p;           break;
                case 1:  i = t;           break;
                case 2:  i = sib;         break;
                case 3:  i = 2 * t + 1;   break;
                case 4:  i = 2 * t + 2;   break;
                case 5:  i = 2 * sib + 1; break;
                case 6:  i = 2 * sib + 2; break;
                case 7:  i = 4 * t + 3;   break;
                case 8:  i = 4 * t + 4;   break;
                case 9:  i = 4 * t + 5;   break;
                default: i = 4 * t + 6;   break;
            }
            if (i < NN) {
                float s_i = (i == 0) ? sa[0]
                          : scp[i] * sa[(i - 1) >> 1] + sct[i] * sa[i];
                float v;
                if (i == 0) v = s_i - 1.f;
                else {
                    int q = (i - 1) >> 1;
                    float s_q = (q == 0) ? sa[0]
                              : scp[q] * sa[(q - 1) >> 1] + sct[q] * sa[q];
                    v = s_i - s_q;
                }
                viol[i] = v;
                if (lane < 5) san[i] = s_i;   // the 5 nodes whose a_node changed
            }
        }
        __syncwarp();
    }
    for (int i = lane; i < NN; i += 32) g_anode[i] = san[i];
}

// ================= K4: out = clip(q_node, 0, a_node), float4 + smem a_node =================
__global__ void __launch_bounds__(256) k_clip(float* __restrict__ out) {
    __shared__ float sA[NN];
    int tid = threadIdx.x;
    sA[tid] = g_anode[tid];
    if (tid < NN - 256) sA[tid + 256] = g_anode[tid + 256];
    __syncthreads();
    int i4 = blockIdx.x * 256 + tid;
    if (i4 < (BATCH * NN) / 4) {
        int base = 4 * i4;
        int n0 = base % NN;
        int n1 = (n0 + 1 == NN) ? 0 : n0 + 1;
        int n2 = (n1 + 1 == NN) ? 0 : n1 + 1;
        int n3 = (n2 + 1 == NN) ? 0 : n2 + 1;
        float4 q = ((const float4*)g_qnode)[i4];
        float4 r;
        r.x = fminf(fmaxf(q.x, 0.f), sA[n0]);
        r.y = fminf(fmaxf(q.y, 0.f), sA[n1]);
        r.z = fminf(fmaxf(q.z, 0.f), sA[n2]);
        r.w = fminf(fmaxf(q.w, 0.f), sA[n3]);
        ((float4*)out)[i4] = r;
    }
}

extern "C" void kernel_launch(void* const* d_in, const int* in_sizes, int n_in,
                              void* d_out, int out_size) {
    const float* x = (const float*)d_in[0];
    const float* W = (const float*)d_in[1];
    const float* b = (const float*)d_in[2];
    float* out = (float*)d_out;

    k_gemm<<<dim3(4, 8, 8), 256>>>(x, W);
    k_ga<<<NN, 128>>>(b);
    k_scan<<<1, 512>>>();
    k_clip<<<((BATCH * NN) / 4 + 255) / 256, 256>>>(out);
}